// round 10
// baseline (speedup 1.0000x reference)
#include <cuda_runtime.h>
#include <math.h>

#define N 1024
#define NN (N*N)
#define NB 64
#define NPAN 16

// ---------------- scratch (device globals) -------------------------------------
__device__ float g_lu[16 * NN];           // LU workspace
__device__ float g_u12[16 * NB * N];      // staged U12 per step
__device__ float g_l21[16 * N * NB];      // staged L21 (position-major)
__device__ float g_diag[16 * NB * 65];    // factored 64x64 diag block (L\U)
__device__ float g_invd[16 * NB];         // 1/U11 diag
__device__ int   g_rowmap[16 * N];        // logical->physical row map
__device__ float g_y[3 * NN];
__device__ float g_part[4 * NN];
__device__ float g_scores[16];
__device__ int   g_top[8];
__device__ int   g_gate;
__device__ float g_weff[11];

// ---------------- init: copy x, identity map -----------------------------------
__global__ void init_kernel(const float4* __restrict__ x4) {
    size_t n4 = (size_t)16 * NN / 4;
    for (size_t i = (size_t)blockIdx.x * blockDim.x + threadIdx.x; i < n4;
         i += (size_t)gridDim.x * blockDim.x)
        ((float4*)g_lu)[i] = x4[i];
    for (int i = blockIdx.x * blockDim.x + threadIdx.x; i < 16 * N;
         i += gridDim.x * blockDim.x)
        g_rowmap[i] = i & (N - 1);
}

// ---------------- panel: window-pivoted 128x64 factor in smem ------------------
__global__ __launch_bounds__(256) void panel_kernel(int kb) {
    __shared__ float sp[128][65];
    int m = blockIdx.x, tid = threadIdx.x, lane = tid & 31;
    int col0 = kb * NB;
    int Ru = N - col0;
    int Wn = Ru < 128 ? Ru : 128;
    float* A = g_lu + (size_t)m * NN;
    int* map = g_rowmap + m * N;

    for (int l = tid; l < Wn * 64; l += 256) {
        int w = l >> 6, c = l & 63;
        sp[w][c] = A[(size_t)map[col0 + w] * N + col0 + c];
    }
    __syncthreads();

    float logsum = 0.0f;
    for (int j = 0; j < 64; j++) {
        // redundant per-warp argmax over window rows >= j (4 rows per lane)
        float bv = -1.0f; int bp = 1 << 30;
        #pragma unroll
        for (int q = 0; q < 4; q++) {
            int w = lane + 32 * q;
            if (w >= j && w < Wn) {
                float v = fabsf(sp[w][j]);
                if (v > bv || (v == bv && w < bp)) { bv = v; bp = w; }
            }
        }
        #pragma unroll
        for (int off = 16; off; off >>= 1) {
            float ov = __shfl_xor_sync(0xffffffffu, bv, off);
            int   op = __shfl_xor_sync(0xffffffffu, bp, off);
            if (ov > bv || (ov == bv && op < bp)) { bv = ov; bp = op; }
        }
        int piv = bp;
        float pv = sp[piv][j];            // read BEFORE any swap
        float inv = 1.0f / pv;
        if (tid == 0) logsum += logf(fabsf(pv));
        __syncthreads();                  // BAR1: reads of col j done
        if (piv != j) {
            if (tid < 64) {
                float t = sp[j][tid];
                sp[j][tid] = sp[piv][tid];
                sp[piv][tid] = t;
            }
            if (tid == 0) {
                int t = map[col0 + j];
                map[col0 + j] = map[col0 + piv];
                map[col0 + piv] = t;
            }
        }
        __syncthreads();                  // BAR2: swap visible
        int r = j + 1 + tid;
        if (r < Wn) {
            float lij = sp[r][j] * inv;
            sp[r][j] = lij;
            for (int c = j + 1; c < 64; c++)
                sp[r][c] -= lij * sp[j][c];
        }
        __syncthreads();                  // BAR3: update visible
    }

    if (tid == 0) {
        if (kb == 0) g_scores[m] = logsum;
        else         g_scores[m] += logsum;
    }
    // diag block + inverse diag
    for (int l = tid; l < 64 * 64; l += 256)
        g_diag[m * NB * 65 + (l >> 6) * 65 + (l & 63)] = sp[l >> 6][l & 63];
    if (tid < 64) g_invd[m * NB + tid] = 1.0f / sp[tid][tid];
    // L rows for window positions 0 .. Wn-65 (window rows 64..Wn-1)
    for (int l = tid; l < (Wn - 64) * 64; l += 256) {
        int p = l >> 6, c = l & 63;
        g_l21[((size_t)m * N + p) * NB + c] = sp[p + 64][c];
    }
}

// ---------------- lstage: U12 = L11^-1 A12 ; L21 = A21 U11^-1 ------------------
// blocked 32+32 register-resident triangular solves (depth 64)
__global__ __launch_bounds__(128) void lstage_kernel(int kb, int ct) {
    __shared__ float d[64][65];
    __shared__ float dinv[64];
    int m = blockIdx.y, tid = threadIdx.x;
    int col0 = kb * NB, nb0 = col0 + NB;
    for (int l = tid; l < 64 * 65; l += 128)
        ((float*)d)[l] = g_diag[m * NB * 65 + l];
    if (tid < 64) dinv[tid] = g_invd[m * NB + tid];
    __syncthreads();
    const int* map = g_rowmap + m * N;
    const float* A = g_lu + (size_t)m * NN;

    if (blockIdx.x < ct) {
        // ---- column solve: U12 column cc ----
        int cc = nb0 + blockIdx.x * 128 + tid;
        if (cc < N) {
            float* U = g_u12 + (size_t)m * NB * N;
            float u1[32], u2[32];
            #pragma unroll
            for (int j = 0; j < 32; j++) {
                float s = A[(size_t)map[col0 + j] * N + cc];
                #pragma unroll 31
                for (int i = 0; i < 31; i++)
                    if (i < j) s -= d[j][i] * u1[i];
                u1[j] = s;
                U[j * N + cc] = s;
            }
            #pragma unroll
            for (int j = 0; j < 32; j++) {
                int jj = 32 + j;
                float s = A[(size_t)map[col0 + jj] * N + cc];
                float t0 = 0.f, t1 = 0.f, t2 = 0.f, t3 = 0.f;
                #pragma unroll
                for (int i = 0; i < 32; i += 4) {
                    t0 += d[jj][i] * u1[i];
                    t1 += d[jj][i + 1] * u1[i + 1];
                    t2 += d[jj][i + 2] * u1[i + 2];
                    t3 += d[jj][i + 3] * u1[i + 3];
                }
                s -= (t0 + t1) + (t2 + t3);
                #pragma unroll 31
                for (int i = 0; i < 31; i++)
                    if (i < j) s -= d[jj][32 + i] * u2[i];
                u2[j] = s;
                U[jj * N + cc] = s;
            }
        }
    } else {
        // ---- row solve: L21 row lr (xv * U11 = a) ----
        int lr = col0 + 128 + (blockIdx.x - ct) * 128 + tid;
        if (lr < N) {
            const float* ar = A + (size_t)map[lr] * N + col0;
            float* lrow = g_l21 + ((size_t)m * N + (lr - nb0)) * NB;
            float x1[32], x2[32];
            #pragma unroll
            for (int j = 0; j < 32; j++) {
                float s = ar[j];
                #pragma unroll 31
                for (int i = 0; i < 31; i++)
                    if (i < j) s -= x1[i] * d[i][j];
                x1[j] = s * dinv[j];
                lrow[j] = x1[j];
            }
            #pragma unroll
            for (int j = 0; j < 32; j++) {
                int jj = 32 + j;
                float s = ar[jj];
                float t0 = 0.f, t1 = 0.f, t2 = 0.f, t3 = 0.f;
                #pragma unroll
                for (int i = 0; i < 32; i += 4) {
                    t0 += x1[i] * d[i][jj];
                    t1 += x1[i + 1] * d[i + 1][jj];
                    t2 += x1[i + 2] * d[i + 2][jj];
                    t3 += x1[i + 3] * d[i + 3][jj];
                }
                s -= (t0 + t1) + (t2 + t3);
                #pragma unroll 31
                for (int i = 0; i < 31; i++)
                    if (i < j) s -= x2[i] * d[32 + i][jj];
                x2[j] = s * dinv[jj];
                lrow[jj] = x2[j];
            }
        }
    }
}

// ---------------- update: A22 -= L21 @ U12, K=64 via two 32-chunks -------------
__global__ __launch_bounds__(256, 2) void update_kernel(int kb) {
    __shared__ float Bs[32][128];
    __shared__ float LsT[32][132];
    int m = blockIdx.z, tid = threadIdx.x;
    int col0 = kb * NB, nb0 = col0 + NB;
    int RC = N - nb0;
    const int* map = g_rowmap + m * N;
    float* A = g_lu + (size_t)m * NN;
    const float* U = g_u12 + (size_t)m * NB * N;
    const float* L = g_l21 + (size_t)m * N * NB;
    int c0 = nb0 + blockIdx.x * 128;
    int r0p = blockIdx.y * 128;
    int tx = tid & 15, ty = tid >> 4;
    float acc[8][8] = {};

    #pragma unroll
    for (int kc = 0; kc < 64; kc += 32) {
        #pragma unroll
        for (int i = 0; i < 16; i++) {
            int l = tid + i * 256;
            int c = l & 127, kk = l >> 7;
            int cc = c0 + c;
            Bs[kk][c] = (cc < N) ? U[(size_t)(kc + kk) * N + cc] : 0.0f;
        }
        #pragma unroll
        for (int i = 0; i < 16; i++) {
            int l = tid + i * 256;
            int r = l >> 5, kk = l & 31;
            int p = r0p + r;
            LsT[kk][r] = (p < RC) ? L[(size_t)p * NB + kc + kk] : 0.0f;
        }
        __syncthreads();
        #pragma unroll
        for (int kk = 0; kk < 32; kk++) {
            float a[8], b[8];
            *(float4*)&a[0] = *(const float4*)&LsT[kk][ty * 8];
            *(float4*)&a[4] = *(const float4*)&LsT[kk][ty * 8 + 4];
            *(float4*)&b[0] = *(const float4*)&Bs[kk][tx * 8];
            *(float4*)&b[4] = *(const float4*)&Bs[kk][tx * 8 + 4];
            #pragma unroll
            for (int i = 0; i < 8; i++)
                #pragma unroll
                for (int j = 0; j < 8; j++)
                    acc[i][j] = fmaf(a[i], b[j], acc[i][j]);
        }
        __syncthreads();
    }
    int gc0 = c0 + tx * 8;
    if (gc0 < N) {
        #pragma unroll
        for (int i = 0; i < 8; i++) {
            int p = r0p + ty * 8 + i;
            if (p < RC) {
                float4* pp = (float4*)&A[(size_t)map[nb0 + p] * N + gc0];
                float4 v0 = pp[0], v1 = pp[1];
                v0.x -= acc[i][0]; v0.y -= acc[i][1]; v0.z -= acc[i][2]; v0.w -= acc[i][3];
                v1.x -= acc[i][4]; v1.y -= acc[i][5]; v1.z -= acc[i][6]; v1.w -= acc[i][7];
                pp[0] = v0; pp[1] = v1;
            }
        }
    }
}

// ---------------- top-8 + effective-weight collapse ----------------------------
__global__ void topk_kernel(const int* __restrict__ flags_i32,
                            const float* __restrict__ W1, const float* __restrict__ b1,
                            const float* __restrict__ W2, const float* __restrict__ b2) {
    if (threadIdx.x != 0) return;
    const unsigned char* flags_u8 = (const unsigned char*)flags_i32;
    int w0 = flags_i32[0];
    bool as_bytes = (w0 > 1) || (w0 < 0);
    int f[16];
    for (int i = 0; i < 16; i++)
        f[i] = as_bytes ? (flags_u8[i] != 0) : (flags_i32[i] != 0);
    int s = 0;
    for (int i = 0; i < 16; i++) s += f[i];
    g_gate = (s >= 4) ? 1 : 0;
    const float NEG_INF = -__int_as_float(0x7f800000);
    float sc[16];
    for (int i = 0; i < 16; i++) sc[i] = f[i] ? g_scores[i] : NEG_INF;
    bool used[16] = {};
    for (int k = 0; k < 8; k++) {
        float best = NEG_INF;
        int bi = -1;
        for (int i = 0; i < 16; i++)
            if (!used[i] && (bi < 0 || sc[i] > best)) { best = sc[i]; bi = i; }
        used[bi] = true;
        g_top[k] = bi;
    }
    for (int c = 0; c < 10; c++) {
        float a = 0.0f;
        for (int h = 0; h < 16; h++) a += W2[h] * W1[h * 10 + c];
        g_weff[c] = a;
    }
    float be = b2[0];
    for (int h = 0; h < 16; h++) be += W2[h] * b1[h];
    g_weff[10] = be;
}

// ---------------- Y combos -----------------------------------------------------
__global__ void ycombo_kernel(const float* __restrict__ x) {
    const float* X1 = x + (size_t)g_top[1] * NN;
    const float* X2 = x + (size_t)g_top[2] * NN;
    const float* X3 = x + (size_t)g_top[3] * NN;
    float w0 = g_weff[0], w1 = g_weff[1], w2 = g_weff[2];
    float w3 = g_weff[3], w4 = g_weff[4], w5 = g_weff[5];
    for (int e = blockIdx.x * blockDim.x + threadIdx.x; e < NN;
         e += gridDim.x * blockDim.x) {
        float a = X1[e], b = X2[e], c = X3[e];
        g_y[e]          = w0 * a + w1 * b + w2 * c;
        g_y[NN + e]     = w3 * b + w4 * c;
        g_y[2 * NN + e] = w5 * c;
    }
}

// ---------------- pair GEMM: X (1024x3072) @ Y (3072x1024), split-K=4 ----------
__global__ __launch_bounds__(256) void pair_gemm(const float* __restrict__ x) {
    __shared__ float As[16][132];
    __shared__ float Bs[16][128];
    int z = blockIdx.z;
    int row0 = blockIdx.y * 128, c0 = blockIdx.x * 128;
    const float* A0 = x + (size_t)g_top[0] * NN;
    const float* A1 = x + (size_t)g_top[1] * NN;
    const float* A2 = x + (size_t)g_top[2] * NN;
    int tid = threadIdx.x;
    float acc[8][8] = {};
    int k0 = z * 768;
    for (int kt = 0; kt < 48; kt++) {
        int kg = k0 + kt * 16;
        const float* Ap = (kg < 1024) ? A0 : ((kg < 2048) ? A1 : A2);
        int kl = kg & 1023;
        #pragma unroll
        for (int i = 0; i < 8; i++) {
            int l = tid + i * 256;
            int kk = l & 15, mm = l >> 4;
            As[kk][mm] = Ap[(size_t)(row0 + mm) * N + kl + kk];
        }
        #pragma unroll
        for (int i = 0; i < 8; i++) {
            int l = tid + i * 256;
            int nn = l & 127, kk = l >> 7;
            Bs[kk][nn] = g_y[(size_t)(kg + kk) * N + c0 + nn];
        }
        __syncthreads();
        int mm0 = (tid >> 4) * 8, nn0 = (tid & 15) * 8;
        #pragma unroll
        for (int kk = 0; kk < 16; kk++) {
            float a[8], b[8];
            *(float4*)&a[0] = *(const float4*)&As[kk][mm0];
            *(float4*)&a[4] = *(const float4*)&As[kk][mm0 + 4];
            *(float4*)&b[0] = *(const float4*)&Bs[kk][nn0];
            *(float4*)&b[4] = *(const float4*)&Bs[kk][nn0 + 4];
            #pragma unroll
            for (int i = 0; i < 8; i++)
                #pragma unroll
                for (int j = 0; j < 8; j++)
                    acc[i][j] = fmaf(a[i], b[j], acc[i][j]);
        }
        __syncthreads();
    }
    float* P = g_part + (size_t)z * NN;
    int mm0 = (tid >> 4) * 8, nn0 = (tid & 15) * 8;
    #pragma unroll
    for (int i = 0; i < 8; i++) {
        float4 v0 = {acc[i][0], acc[i][1], acc[i][2], acc[i][3]};
        float4 v1 = {acc[i][4], acc[i][5], acc[i][6], acc[i][7]};
        size_t off = (size_t)(row0 + mm0 + i) * N + c0 + nn0;
        *(float4*)&P[off] = v0;
        *(float4*)&P[off + 4] = v1;
    }
}

// ---------------- epilogue -----------------------------------------------------
__global__ void final_kernel(const float* __restrict__ x, float* __restrict__ out,
                             int out_size) {
    int gate = g_gate;
    const float* P4 = x + (size_t)g_top[4] * NN;
    const float* P5 = x + (size_t)g_top[5] * NN;
    const float* P6 = x + (size_t)g_top[6] * NN;
    const float* P7 = x + (size_t)g_top[7] * NN;
    float w6 = g_weff[6], w7 = g_weff[7], w8 = g_weff[8], w9 = g_weff[9];
    float be = g_weff[10];
    for (int i = blockIdx.x * blockDim.x + threadIdx.x; i < out_size;
         i += gridDim.x * blockDim.x) {
        if (i < NN) {
            float s = g_part[i] + g_part[NN + i] + g_part[2 * NN + i] + g_part[3 * NN + i]
                    + w6 * P4[i] + w7 * P5[i] + w8 * P6[i] + w9 * P7[i] + be;
            out[i] = gate ? (s / (1.0f + expf(-s))) : 0.0f;
        } else {
            out[i] = gate ? 1.0f : 0.0f;
        }
    }
}

// ---------------- host driver --------------------------------------------------
extern "C" void kernel_launch(void* const* d_in, const int* in_sizes, int n_in,
                              void* d_out, int out_size) {
    const float* x = (const float*)d_in[0];
    const int* flags = (const int*)d_in[1];
    const float* W1 = (const float*)d_in[2];
    const float* b1 = (const float*)d_in[3];
    const float* W2 = (const float*)d_in[4];
    const float* b2 = (const float*)d_in[5];
    float* out = (float*)d_out;

    init_kernel<<<2048, 256>>>((const float4*)x);

    for (int kb = 0; kb < NPAN; kb++) {
        panel_kernel<<<16, 256>>>(kb);
        int CC = N - NB * (kb + 1);
        if (CC > 0) {
            int Ru = N - NB * kb;
            int ct = (CC + 127) / 128;
            int rtB = (Ru > 128) ? (Ru - 128 + 127) / 128 : 0;
            lstage_kernel<<<dim3(ct + rtB, 16), 128>>>(kb, ct);
            update_kernel<<<dim3(ct, ct, 16), 256>>>(kb);
        }
    }

    topk_kernel<<<1, 32>>>(flags, W1, b1, W2, b2);
    ycombo_kernel<<<1024, 256>>>(x);
    pair_gemm<<<dim3(8, 8, 4), 256>>>(x);
    final_kernel<<<1024, 256>>>(x, out, out_size);
}

// round 11
// speedup vs baseline: 1.0199x; 1.0199x over previous
#include <cuda_runtime.h>
#include <math.h>

#define N 1024
#define NN (N*N)
#define NB 32
#define NPAN 28      // panels 0..27; last 128 cols factored by tail_kernel

// ---------------- scratch (device globals) -------------------------------------
__device__ float g_lu[16 * NN];          // LU workspace
__device__ float g_u12[16 * 32 * N];     // staged U12 per step
__device__ float g_l21[16 * N * 32];     // staged L21 (position-major)
__device__ float g_diag[16 * 32 * 33];   // factored 32x32 diag block (L\U)
__device__ float g_invd[16 * 32];        // 1/U11 diag
__device__ int   g_rowmap[16 * N];       // logical->physical row map
__device__ float g_part[8 * NN];         // split-K partials
__device__ float g_scores[16];
__device__ int   g_top[8];
__device__ int   g_gate;
__device__ float g_weff[11];

// ---------------- init: copy x, identity map -----------------------------------
__global__ void init_kernel(const float4* __restrict__ x4) {
    size_t n4 = (size_t)16 * NN / 4;
    for (size_t i = (size_t)blockIdx.x * blockDim.x + threadIdx.x; i < n4;
         i += (size_t)gridDim.x * blockDim.x)
        ((float4*)g_lu)[i] = x4[i];
    for (int i = blockIdx.x * blockDim.x + threadIdx.x; i < 16 * N;
         i += gridDim.x * blockDim.x)
        g_rowmap[i] = i & (N - 1);
}

// ---------------- panel: window-pivoted 128x32 factor in smem ------------------
__global__ __launch_bounds__(256) void panel_kernel(int kb) {
    __shared__ float sp[128][33];
    int m = blockIdx.x, tid = threadIdx.x, lane = tid & 31;
    int col0 = kb * NB;
    int Ru = N - col0;
    int Wn = Ru < 128 ? Ru : 128;
    float* A = g_lu + (size_t)m * NN;
    int* map = g_rowmap + m * N;

    for (int l = tid; l < Wn * 32; l += 256) {
        int w = l >> 5, c = l & 31;
        sp[w][c] = A[(size_t)map[col0 + w] * N + col0 + c];
    }
    __syncthreads();

    float logsum = 0.0f;
    for (int j = 0; j < 32; j++) {
        float bv = -1.0f; int bp = 1 << 30;
        #pragma unroll
        for (int q = 0; q < 4; q++) {
            int w = lane + 32 * q;
            if (w >= j && w < Wn) {
                float v = fabsf(sp[w][j]);
                if (v > bv || (v == bv && w < bp)) { bv = v; bp = w; }
            }
        }
        #pragma unroll
        for (int off = 16; off; off >>= 1) {
            float ov = __shfl_xor_sync(0xffffffffu, bv, off);
            int   op = __shfl_xor_sync(0xffffffffu, bp, off);
            if (ov > bv || (ov == bv && op < bp)) { bv = ov; bp = op; }
        }
        int piv = bp;
        float pv = sp[piv][j];
        float inv = 1.0f / pv;
        if (tid == 0) logsum += logf(fabsf(pv));
        __syncthreads();
        if (piv != j) {
            if (tid < 32) {
                float t = sp[j][tid];
                sp[j][tid] = sp[piv][tid];
                sp[piv][tid] = t;
            }
            if (tid == 0) {
                int t = map[col0 + j];
                map[col0 + j] = map[col0 + piv];
                map[col0 + piv] = t;
            }
        }
        __syncthreads();
        int r = j + 1 + tid;
        if (r < Wn) {
            float lij = sp[r][j] * inv;
            sp[r][j] = lij;
            for (int c = j + 1; c < 32; c++)
                sp[r][c] -= lij * sp[j][c];
        }
        __syncthreads();
    }

    if (tid == 0) {
        if (kb == 0) g_scores[m] = logsum;
        else         g_scores[m] += logsum;
    }
    for (int l = tid; l < 32 * 32; l += 256)
        g_diag[m * 32 * 33 + (l >> 5) * 33 + (l & 31)] = sp[l >> 5][l & 31];
    if (tid < 32) g_invd[m * 32 + tid] = 1.0f / sp[tid][tid];
    for (int l = tid; l < (Wn - 32) * 32; l += 256) {
        int p = l >> 5, c = l & 31;
        g_l21[((size_t)m * N + p) * 32 + c] = sp[p + 32][c];
    }
}

// ---------------- lstage: U12 = L11^-1 A12 ; L21 = A21 U11^-1 ------------------
__global__ __launch_bounds__(128) void lstage_kernel(int kb, int ct) {
    __shared__ float d[32][33];
    __shared__ float dinv[32];
    int m = blockIdx.y, tid = threadIdx.x;
    int col0 = kb * NB, nb0 = col0 + NB;
    for (int l = tid; l < 32 * 33; l += 128)
        ((float*)d)[l] = g_diag[m * 32 * 33 + l];
    if (tid < 32) dinv[tid] = g_invd[m * 32 + tid];
    __syncthreads();
    const int* map = g_rowmap + m * N;
    const float* A = g_lu + (size_t)m * NN;

    if (blockIdx.x < ct) {
        int cc = nb0 + blockIdx.x * 128 + tid;
        if (cc < N) {
            float u[32];
            float* U = g_u12 + (size_t)m * 32 * N;
            #pragma unroll
            for (int j = 0; j < 32; j++) {
                float s = A[(size_t)map[col0 + j] * N + cc];
                #pragma unroll 31
                for (int i = 0; i < 31; i++)
                    if (i < j) s -= d[j][i] * u[i];
                u[j] = s;
                U[j * N + cc] = s;
            }
        }
    } else {
        int lr = col0 + 128 + (blockIdx.x - ct) * 128 + tid;
        if (lr < N) {
            const float* ar = A + (size_t)map[lr] * N + col0;
            float* lrow = g_l21 + ((size_t)m * N + (lr - nb0)) * 32;
            float xv[32];
            #pragma unroll
            for (int j = 0; j < 32; j++) {
                float s = ar[j];
                #pragma unroll 31
                for (int i = 0; i < 31; i++)
                    if (i < j) s -= xv[i] * d[i][j];
                xv[j] = s * dinv[j];
                lrow[j] = xv[j];
            }
        }
    }
}

// ---------------- update: A22 -= L21 @ U12 (128x128 tiles, 2 CTA/SM) -----------
__global__ __launch_bounds__(256, 2) void update_kernel(int kb) {
    __shared__ float Bs[32][128];
    __shared__ float LsT[32][132];
    int m = blockIdx.z, tid = threadIdx.x;
    int col0 = kb * NB, nb0 = col0 + NB;
    int RC = N - nb0;
    const int* map = g_rowmap + m * N;
    float* A = g_lu + (size_t)m * NN;
    const float* U = g_u12 + (size_t)m * 32 * N;
    const float* L = g_l21 + (size_t)m * N * 32;
    int c0 = nb0 + blockIdx.x * 128;
    int r0p = blockIdx.y * 128;

    #pragma unroll
    for (int i = 0; i < 16; i++) {
        int l = tid + i * 256;
        int c = l & 127, kk = l >> 7;
        int cc = c0 + c;
        Bs[kk][c] = (cc < N) ? U[kk * N + cc] : 0.0f;
    }
    #pragma unroll
    for (int i = 0; i < 16; i++) {
        int l = tid + i * 256;
        int r = l >> 5, kk = l & 31;
        int p = r0p + r;
        LsT[kk][r] = (p < RC) ? L[(size_t)p * 32 + kk] : 0.0f;
    }
    __syncthreads();

    int tx = tid & 15, ty = tid >> 4;
    float acc[8][8] = {};
    #pragma unroll
    for (int kk = 0; kk < 32; kk++) {
        float a[8], b[8];
        *(float4*)&a[0] = *(const float4*)&LsT[kk][ty * 8];
        *(float4*)&a[4] = *(const float4*)&LsT[kk][ty * 8 + 4];
        *(float4*)&b[0] = *(const float4*)&Bs[kk][tx * 8];
        *(float4*)&b[4] = *(const float4*)&Bs[kk][tx * 8 + 4];
        #pragma unroll
        for (int i = 0; i < 8; i++)
            #pragma unroll
            for (int j = 0; j < 8; j++)
                acc[i][j] = fmaf(a[i], b[j], acc[i][j]);
    }
    int gc0 = c0 + tx * 8;
    if (gc0 < N) {
        #pragma unroll
        for (int i = 0; i < 8; i++) {
            int p = r0p + ty * 8 + i;
            if (p < RC) {
                float4* pp = (float4*)&A[(size_t)map[nb0 + p] * N + gc0];
                float4 v0 = pp[0], v1 = pp[1];
                v0.x -= acc[i][0]; v0.y -= acc[i][1]; v0.z -= acc[i][2]; v0.w -= acc[i][3];
                v1.x -= acc[i][4]; v1.y -= acc[i][5]; v1.z -= acc[i][6]; v1.w -= acc[i][7];
                pp[0] = v0; pp[1] = v1;
            }
        }
    }
}

// ---------------- tail: full pivoted factor of trailing 128x128 (logdet) -------
__global__ __launch_bounds__(256) void tail_kernel() {
    extern __shared__ float st[];         // 128 x 132
    __shared__ float rv[8];
    __shared__ int   rr[8];
    __shared__ float s_u;
    __shared__ int   s_p;
    int m = blockIdx.x, tid = threadIdx.x;
    const float* A = g_lu + (size_t)m * NN;
    const int* map = g_rowmap + m * N;
    const int nb0 = N - 128;              // 896

    for (int l = tid; l < 128 * 128; l += 256) {
        int r = l >> 7, c = l & 127;
        st[r * 132 + c] = A[(size_t)map[nb0 + r] * N + nb0 + c];
    }
    __syncthreads();

    float logsum = 0.0f;
    for (int j = 0; j < 128; j++) {
        float bv = -1.0f; int br = j;
        if (tid < 128 && tid >= j) {
            bv = fabsf(st[tid * 132 + j]);
            br = tid;
        }
        #pragma unroll
        for (int off = 16; off; off >>= 1) {
            float ov = __shfl_down_sync(0xffffffffu, bv, off);
            int   orr = __shfl_down_sync(0xffffffffu, br, off);
            if (ov > bv || (ov == bv && orr < br)) { bv = ov; br = orr; }
        }
        if ((tid & 31) == 0) { rv[tid >> 5] = bv; rr[tid >> 5] = br; }
        __syncthreads();
        if (tid == 0) {
            float b0 = rv[0]; int r0 = rr[0];
            for (int w = 1; w < 8; w++)
                if (rv[w] > b0 || (rv[w] == b0 && rr[w] < r0)) { b0 = rv[w]; r0 = rr[w]; }
            s_p = r0;
            s_u = st[r0 * 132 + j];
            logsum += logf(fabsf(s_u));
        }
        __syncthreads();
        int p = s_p;
        float u = s_u;
        if (tid < 128 && p != j) {
            float t = st[j * 132 + tid];
            st[j * 132 + tid] = st[p * 132 + tid];
            st[p * 132 + tid] = t;
        }
        __syncthreads();
        if (tid < 128 && tid > j) {
            float lij = st[tid * 132 + j] / u;
            for (int c = j + 1; c < 128; c++)
                st[tid * 132 + c] -= lij * st[j * 132 + c];
        }
        __syncthreads();
    }
    if (tid == 0) g_scores[m] += logsum;
}

// ---------------- top-8 + effective-weight collapse ----------------------------
__global__ void topk_kernel(const int* __restrict__ flags_i32,
                            const float* __restrict__ W1, const float* __restrict__ b1,
                            const float* __restrict__ W2, const float* __restrict__ b2) {
    if (threadIdx.x != 0) return;
    const unsigned char* flags_u8 = (const unsigned char*)flags_i32;
    int w0 = flags_i32[0];
    bool as_bytes = (w0 > 1) || (w0 < 0);
    int f[16];
    for (int i = 0; i < 16; i++)
        f[i] = as_bytes ? (flags_u8[i] != 0) : (flags_i32[i] != 0);
    int s = 0;
    for (int i = 0; i < 16; i++) s += f[i];
    g_gate = (s >= 4) ? 1 : 0;
    const float NEG_INF = -__int_as_float(0x7f800000);
    float sc[16];
    for (int i = 0; i < 16; i++) sc[i] = f[i] ? g_scores[i] : NEG_INF;
    bool used[16] = {};
    for (int k = 0; k < 8; k++) {
        float best = NEG_INF;
        int bi = -1;
        for (int i = 0; i < 16; i++)
            if (!used[i] && (bi < 0 || sc[i] > best)) { best = sc[i]; bi = i; }
        used[bi] = true;
        g_top[k] = bi;
    }
    for (int c = 0; c < 10; c++) {
        float a = 0.0f;
        for (int h = 0; h < 16; h++) a += W2[h] * W1[h * 10 + c];
        g_weff[c] = a;
    }
    float be = b2[0];
    for (int h = 0; h < 16; h++) be += W2[h] * b1[h];
    g_weff[10] = be;
}

// ---------------- pair GEMM with fused Y combos, split-K=8 ---------------------
// D = X(1024x3072) @ Y(3072x1024); Y rows built on the fly:
//   kg <1024 : w0*X1 + w1*X2 + w2*X3   (row kg)
//   kg <2048 : w3*X2 + w4*X3           (row kg-1024)
//   else     : w5*X3                   (row kg-2048)
__global__ __launch_bounds__(256) void pair_gemm(const float* __restrict__ x) {
    __shared__ float As[16][132];
    __shared__ float Bs[16][128];
    int z = blockIdx.z;
    int row0 = blockIdx.y * 128, c0 = blockIdx.x * 128;
    const float* A0 = x + (size_t)g_top[0] * NN;
    const float* A1 = x + (size_t)g_top[1] * NN;
    const float* A2 = x + (size_t)g_top[2] * NN;
    const float* X1 = A1;
    const float* X2 = x + (size_t)g_top[2] * NN;
    const float* X3 = x + (size_t)g_top[3] * NN;
    float w0 = g_weff[0], w1 = g_weff[1], w2 = g_weff[2];
    float w3 = g_weff[3], w4 = g_weff[4], w5 = g_weff[5];
    int tid = threadIdx.x;
    float acc[8][8] = {};
    int k0 = z * 384;
    for (int kt = 0; kt < 24; kt++) {
        int kgb = k0 + kt * 16;
        const float* Ap = (kgb < 1024) ? A0 : ((kgb < 2048) ? A1 : A2);
        int kl = kgb & 1023;
        #pragma unroll
        for (int i = 0; i < 8; i++) {
            int l = tid + i * 256;
            int kk = l & 15, mm = l >> 4;
            As[kk][mm] = Ap[(size_t)(row0 + mm) * N + kl + kk];
        }
        #pragma unroll
        for (int i = 0; i < 8; i++) {
            int l = tid + i * 256;
            int nn = l & 127, kk = l >> 7;
            size_t off = (size_t)(kl + kk) * N + c0 + nn;
            float v;
            if (kgb < 1024)      v = w0 * X1[off] + w1 * X2[off] + w2 * X3[off];
            else if (kgb < 2048) v = w3 * X2[off] + w4 * X3[off];
            else                 v = w5 * X3[off];
            Bs[kk][nn] = v;
        }
        __syncthreads();
        int mm0 = (tid >> 4) * 8, nn0 = (tid & 15) * 8;
        #pragma unroll
        for (int kk = 0; kk < 16; kk++) {
            float a[8], b[8];
            *(float4*)&a[0] = *(const float4*)&As[kk][mm0];
            *(float4*)&a[4] = *(const float4*)&As[kk][mm0 + 4];
            *(float4*)&b[0] = *(const float4*)&Bs[kk][nn0];
            *(float4*)&b[4] = *(const float4*)&Bs[kk][nn0 + 4];
            #pragma unroll
            for (int i = 0; i < 8; i++)
                #pragma unroll
                for (int j = 0; j < 8; j++)
                    acc[i][j] = fmaf(a[i], b[j], acc[i][j]);
        }
        __syncthreads();
    }
    float* P = g_part + (size_t)z * NN;
    int mm0 = (tid >> 4) * 8, nn0 = (tid & 15) * 8;
    #pragma unroll
    for (int i = 0; i < 8; i++) {
        float4 v0 = {acc[i][0], acc[i][1], acc[i][2], acc[i][3]};
        float4 v1 = {acc[i][4], acc[i][5], acc[i][6], acc[i][7]};
        size_t off = (size_t)(row0 + mm0 + i) * N + c0 + nn0;
        *(float4*)&P[off] = v0;
        *(float4*)&P[off + 4] = v1;
    }
}

// ---------------- epilogue -----------------------------------------------------
__global__ void final_kernel(const float* __restrict__ x, float* __restrict__ out,
                             int out_size) {
    int gate = g_gate;
    const float* P4 = x + (size_t)g_top[4] * NN;
    const float* P5 = x + (size_t)g_top[5] * NN;
    const float* P6 = x + (size_t)g_top[6] * NN;
    const float* P7 = x + (size_t)g_top[7] * NN;
    float w6 = g_weff[6], w7 = g_weff[7], w8 = g_weff[8], w9 = g_weff[9];
    float be = g_weff[10];
    for (int i = blockIdx.x * blockDim.x + threadIdx.x; i < out_size;
         i += gridDim.x * blockDim.x) {
        if (i < NN) {
            float s = ((g_part[i] + g_part[NN + i]) + (g_part[2 * NN + i] + g_part[3 * NN + i]))
                    + ((g_part[4 * NN + i] + g_part[5 * NN + i]) + (g_part[6 * NN + i] + g_part[7 * NN + i]))
                    + w6 * P4[i] + w7 * P5[i] + w8 * P6[i] + w9 * P7[i] + be;
            out[i] = gate ? (s / (1.0f + expf(-s))) : 0.0f;
        } else {
            out[i] = gate ? 1.0f : 0.0f;
        }
    }
}

// ---------------- host driver --------------------------------------------------
extern "C" void kernel_launch(void* const* d_in, const int* in_sizes, int n_in,
                              void* d_out, int out_size) {
    const float* x = (const float*)d_in[0];
    const int* flags = (const int*)d_in[1];
    const float* W1 = (const float*)d_in[2];
    const float* b1 = (const float*)d_in[3];
    const float* W2 = (const float*)d_in[4];
    const float* b2 = (const float*)d_in[5];
    float* out = (float*)d_out;

    const size_t tail_smem = 128 * 132 * 4;   // 67.6 KB
    cudaFuncSetAttribute(tail_kernel, cudaFuncAttributeMaxDynamicSharedMemorySize,
                         tail_smem);

    init_kernel<<<2048, 256>>>((const float4*)x);

    for (int kb = 0; kb < NPAN; kb++) {
        panel_kernel<<<16, 256>>>(kb);
        int CC = N - NB * (kb + 1);        // >= 128 for kb <= 27
        int Ru = N - NB * kb;
        int ct = (CC + 127) / 128;
        int rtB = (Ru > 128) ? (Ru - 128 + 127) / 128 : 0;
        lstage_kernel<<<dim3(ct + rtB, 16), 128>>>(kb, ct);
        update_kernel<<<dim3(ct, ct, 16), 256>>>(kb);
    }

    tail_kernel<<<16, 256, tail_smem>>>();
    topk_kernel<<<1, 32>>>(flags, W1, b1, W2, b2);
    pair_gemm<<<dim3(8, 8, 8), 256>>>(x);
    final_kernel<<<1024, 256>>>(x, out, out_size);
}

// round 13
// speedup vs baseline: 1.5993x; 1.5680x over previous
#include <cuda_runtime.h>
#include <math.h>

#define N 1024
#define NN (N*N)
#define NB 32
#define NPAN 28      // panels 0..27; last 128 cols by tail phase
#define GPM 18       // CTAs per matrix
#define NMAT 16

// ---------------- scratch (device globals) -------------------------------------
__device__ float g_lu[16 * NN];
__device__ float g_u12[16 * 32 * N];
__device__ float g_l21[16 * N * 32];
__device__ float g_diag[16 * 32 * 33];
__device__ float g_invd[16 * 32];
__device__ int   g_rowmap[16 * N];
__device__ float g_y[3 * NN];
__device__ float g_part[4 * NN];
__device__ float g_scores[16];
__device__ int   g_top[8];
__device__ int   g_gate;
__device__ float g_weff[11];
__device__ int   g_barcnt[NMAT];
__device__ int   g_bargen[NMAT];

// ---------------- barrier state reset (graph-replay safe) ----------------------
__global__ void reset_kernel() {
    if (threadIdx.x < NMAT) {
        g_barcnt[threadIdx.x] = 0;
        g_bargen[threadIdx.x] = 0;
    }
}

// ---------------- per-matrix CTA-group barrier ---------------------------------
__device__ __forceinline__ void mbar(int m, int* sgen) {
    __threadfence();
    __syncthreads();
    if (threadIdx.x == 0) {
        int g = *sgen;
        int v = atomicAdd(&g_barcnt[m], 1);
        if (v == GPM - 1) {
            atomicExch(&g_barcnt[m], 0);
            __threadfence();
            atomicExch(&g_bargen[m], g + 1);           // release
        } else {
            while (atomicAdd(&g_bargen[m], 0) < g + 1) __nanosleep(64);
        }
        *sgen = g + 1;
        __threadfence();
    }
    __syncthreads();
}

// ---------------- phase: window-pivoted 128x32 panel (CTA0 only) ---------------
__device__ void panel_phase(int kb, int m, float* smem_f) {
    float (*sp)[33] = (float (*)[33])smem_f;           // 128 x 33
    int tid = threadIdx.x, lane = tid & 31;
    int col0 = kb * NB;
    int Ru = N - col0;
    int Wn = Ru < 128 ? Ru : 128;
    float* A = g_lu + (size_t)m * NN;
    int* map = g_rowmap + m * N;

    for (int l = tid; l < Wn * 32; l += 256) {
        int w = l >> 5, c = l & 31;
        sp[w][c] = A[(size_t)map[col0 + w] * N + col0 + c];
    }
    __syncthreads();

    float logsum = 0.0f;
    for (int j = 0; j < 32; j++) {
        float bv = -1.0f; int bp = 1 << 30;
        #pragma unroll
        for (int q = 0; q < 4; q++) {
            int w = lane + 32 * q;
            if (w >= j && w < Wn) {
                float v = fabsf(sp[w][j]);
                if (v > bv || (v == bv && w < bp)) { bv = v; bp = w; }
            }
        }
        #pragma unroll
        for (int off = 16; off; off >>= 1) {
            float ov = __shfl_xor_sync(0xffffffffu, bv, off);
            int   op = __shfl_xor_sync(0xffffffffu, bp, off);
            if (ov > bv || (ov == bv && op < bp)) { bv = ov; bp = op; }
        }
        int piv = bp;
        float pv = sp[piv][j];
        float inv = 1.0f / pv;
        if (tid == 0) logsum += logf(fabsf(pv));
        __syncthreads();
        if (piv != j) {
            if (tid < 32) {
                float t = sp[j][tid];
                sp[j][tid] = sp[piv][tid];
                sp[piv][tid] = t;
            }
            if (tid == 0) {
                int t = map[col0 + j];
                map[col0 + j] = map[col0 + piv];
                map[col0 + piv] = t;
            }
        }
        __syncthreads();
        int r = j + 1 + tid;
        if (r < Wn) {
            float lij = sp[r][j] * inv;
            sp[r][j] = lij;
            for (int c = j + 1; c < 32; c++)
                sp[r][c] -= lij * sp[j][c];
        }
        __syncthreads();
    }

    if (tid == 0) {
        if (kb == 0) g_scores[m] = logsum;
        else         g_scores[m] += logsum;
    }
    for (int l = tid; l < 32 * 32; l += 256)
        g_diag[m * 32 * 33 + (l >> 5) * 33 + (l & 31)] = sp[l >> 5][l & 31];
    if (tid < 32) g_invd[m * 32 + tid] = 1.0f / sp[tid][tid];
    for (int l = tid; l < (Wn - 32) * 32; l += 256) {
        int p = l >> 5, c = l & 31;
        g_l21[((size_t)m * N + p) * 32 + c] = sp[p + 32][c];
    }
}

// ---------------- phase: U12 = L11^-1 A12 ; L21 = A21 U11^-1 -------------------
__device__ void lstage_phase(int kb, int m, int r, float* smem_f) {
    float (*d)[33] = (float (*)[33])smem_f;            // 32 x 33
    float* dinv = smem_f + 32 * 33;
    int tid = threadIdx.x;
    int col0 = kb * NB, nb0 = col0 + NB;
    for (int l = tid; l < 32 * 33; l += 256)
        ((float*)d)[l] = g_diag[m * 32 * 33 + l];
    if (tid < 32) dinv[tid] = g_invd[m * 32 + tid];
    __syncthreads();
    const int* map = g_rowmap + m * N;
    const float* A = g_lu + (size_t)m * NN;
    int CC = N - nb0;
    int nrows = N - col0 - 128;

    int gid = r * 256 + tid;
    if (gid < CC) {
        int cc = nb0 + gid;
        float u[32];
        float* U = g_u12 + (size_t)m * 32 * N;
        #pragma unroll
        for (int j = 0; j < 32; j++) {
            float s = A[(size_t)map[col0 + j] * N + cc];
            #pragma unroll 31
            for (int i = 0; i < 31; i++)
                if (i < j) s -= d[j][i] * u[i];
            u[j] = s;
            U[j * N + cc] = s;
        }
    } else if (gid - CC < nrows) {
        int lr = col0 + 128 + (gid - CC);
        const float* ar = A + (size_t)map[lr] * N + col0;
        float* lrow = g_l21 + ((size_t)m * N + (lr - nb0)) * 32;
        float xv[32];
        #pragma unroll
        for (int j = 0; j < 32; j++) {
            float s = ar[j];
            #pragma unroll 31
            for (int i = 0; i < 31; i++)
                if (i < j) s -= xv[i] * d[i][j];
            xv[j] = s * dinv[j];
            lrow[j] = xv[j];
        }
    }
}

// ---------------- phase: A22 -= L21 @ U12 (128x128 tiles, strided over group) --
__device__ void update_phase(int kb, int m, int r, float* smem_f) {
    float (*Bs)[128]  = (float (*)[128])smem_f;                 // 32 x 128
    float (*LsT)[132] = (float (*)[132])(smem_f + 32 * 128);    // 32 x 132
    int tid = threadIdx.x;
    int col0 = kb * NB, nb0 = col0 + NB;
    int RC = N - nb0;
    int ct = (RC + 127) >> 7;
    const int* map = g_rowmap + m * N;
    float* A = g_lu + (size_t)m * NN;
    const float* U = g_u12 + (size_t)m * 32 * N;
    const float* L = g_l21 + (size_t)m * N * 32;
    int tx = tid & 15, ty = tid >> 4;

    for (int t = r; t < ct * ct; t += GPM) {
        int c0 = nb0 + (t % ct) * 128;
        int r0p = (t / ct) * 128;

        #pragma unroll
        for (int i = 0; i < 16; i++) {
            int l = tid + i * 256;
            int c = l & 127, kk = l >> 7;
            int cc = c0 + c;
            Bs[kk][c] = (cc < N) ? U[kk * N + cc] : 0.0f;
        }
        #pragma unroll
        for (int i = 0; i < 16; i++) {
            int l = tid + i * 256;
            int rr2 = l >> 5, kk = l & 31;
            int p = r0p + rr2;
            LsT[kk][rr2] = (p < RC) ? L[(size_t)p * 32 + kk] : 0.0f;
        }
        __syncthreads();

        float acc[8][8] = {};
        #pragma unroll
        for (int kk = 0; kk < 32; kk++) {
            float a[8], b[8];
            *(float4*)&a[0] = *(const float4*)&LsT[kk][ty * 8];
            *(float4*)&a[4] = *(const float4*)&LsT[kk][ty * 8 + 4];
            *(float4*)&b[0] = *(const float4*)&Bs[kk][tx * 8];
            *(float4*)&b[4] = *(const float4*)&Bs[kk][tx * 8 + 4];
            #pragma unroll
            for (int i = 0; i < 8; i++)
                #pragma unroll
                for (int j = 0; j < 8; j++)
                    acc[i][j] = fmaf(a[i], b[j], acc[i][j]);
        }
        int gc0 = c0 + tx * 8;
        if (gc0 < N) {
            #pragma unroll
            for (int i = 0; i < 8; i++) {
                int p = r0p + ty * 8 + i;
                if (p < RC) {
                    float4* pp = (float4*)&A[(size_t)map[nb0 + p] * N + gc0];
                    float4 v0 = pp[0], v1 = pp[1];
                    v0.x -= acc[i][0]; v0.y -= acc[i][1]; v0.z -= acc[i][2]; v0.w -= acc[i][3];
                    v1.x -= acc[i][4]; v1.y -= acc[i][5]; v1.z -= acc[i][6]; v1.w -= acc[i][7];
                    pp[0] = v0; pp[1] = v1;
                }
            }
        }
        __syncthreads();
    }
}

// ---------------- phase: full pivoted factor of trailing 128x128 (CTA0) --------
__device__ void tail_phase(int m, float* smem_f) {
    float* st = smem_f;                                  // 128 x 132
    __shared__ float rv[8];
    __shared__ int   rr[8];
    __shared__ float s_u;
    __shared__ int   s_p;
    int tid = threadIdx.x;
    const float* A = g_lu + (size_t)m * NN;
    const int* map = g_rowmap + m * N;
    const int nb0 = N - 128;

    for (int l = tid; l < 128 * 128; l += 256) {
        int r = l >> 7, c = l & 127;
        st[r * 132 + c] = A[(size_t)map[nb0 + r] * N + nb0 + c];
    }
    __syncthreads();

    float logsum = 0.0f;
    for (int j = 0; j < 128; j++) {
        float bv = -1.0f; int br = j;
        if (tid < 128 && tid >= j) {
            bv = fabsf(st[tid * 132 + j]);
            br = tid;
        }
        #pragma unroll
        for (int off = 16; off; off >>= 1) {
            float ov = __shfl_down_sync(0xffffffffu, bv, off);
            int   orr = __shfl_down_sync(0xffffffffu, br, off);
            if (ov > bv || (ov == bv && orr < br)) { bv = ov; br = orr; }
        }
        if ((tid & 31) == 0) { rv[tid >> 5] = bv; rr[tid >> 5] = br; }
        __syncthreads();
        if (tid == 0) {
            float b0 = rv[0]; int r0 = rr[0];
            for (int w = 1; w < 8; w++)
                if (rv[w] > b0 || (rv[w] == b0 && rr[w] < r0)) { b0 = rv[w]; r0 = rr[w]; }
            s_p = r0;
            s_u = st[r0 * 132 + j];
            logsum += logf(fabsf(s_u));
        }
        __syncthreads();
        int p = s_p;
        float u = s_u;
        if (tid < 128 && p != j) {
            float t = st[j * 132 + tid];
            st[j * 132 + tid] = st[p * 132 + tid];
            st[p * 132 + tid] = t;
        }
        __syncthreads();
        if (tid < 128 && tid > j) {
            float lij = st[tid * 132 + j] / u;
            for (int c = j + 1; c < 128; c++)
                st[tid * 132 + c] -= lij * st[j * 132 + c];
        }
        __syncthreads();
    }
    if (tid == 0) g_scores[m] += logsum;
}

// ---------------- persistent LU: 16 matrices x 18 CTAs, all co-resident --------
__global__ __launch_bounds__(256, 2) void lu_persistent(const float4* __restrict__ x4) {
    extern __shared__ float smem[];
    __shared__ int sgen;
    int m = blockIdx.x / GPM;
    int r = blockIdx.x % GPM;
    int tid = threadIdx.x;
    if (tid == 0) sgen = 0;
    __syncthreads();

    // cooperative copy of matrix m + identity rowmap
    const float4* src = x4 + (size_t)m * (NN / 4);
    float4* dst = (float4*)(g_lu + (size_t)m * NN);
    for (int i = r * 256 + tid; i < NN / 4; i += GPM * 256) dst[i] = src[i];
    for (int i = r * 256 + tid; i < N; i += GPM * 256) g_rowmap[m * N + i] = i;
    mbar(m, &sgen);

    for (int kb = 0; kb < NPAN; kb++) {
        if (r == 0) panel_phase(kb, m, smem);
        mbar(m, &sgen);
        lstage_phase(kb, m, r, smem);
        mbar(m, &sgen);
        update_phase(kb, m, r, smem);
        mbar(m, &sgen);
    }
    if (r == 0) tail_phase(m, smem);
}

// ---------------- top-8 + effective-weight collapse ----------------------------
__global__ void topk_kernel(const int* __restrict__ flags_i32,
                            const float* __restrict__ W1, const float* __restrict__ b1,
                            const float* __restrict__ W2, const float* __restrict__ b2) {
    if (threadIdx.x != 0) return;
    const unsigned char* flags_u8 = (const unsigned char*)flags_i32;
    int w0 = flags_i32[0];
    bool as_bytes = (w0 > 1) || (w0 < 0);
    int f[16];
    for (int i = 0; i < 16; i++)
        f[i] = as_bytes ? (flags_u8[i] != 0) : (flags_i32[i] != 0);
    int s = 0;
    for (int i = 0; i < 16; i++) s += f[i];
    g_gate = (s >= 4) ? 1 : 0;
    const float NEG_INF = -__int_as_float(0x7f800000);
    float sc[16];
    for (int i = 0; i < 16; i++) sc[i] = f[i] ? g_scores[i] : NEG_INF;
    bool used[16] = {};
    for (int k = 0; k < 8; k++) {
        float best = NEG_INF;
        int bi = -1;
        for (int i = 0; i < 16; i++)
            if (!used[i] && (bi < 0 || sc[i] > best)) { best = sc[i]; bi = i; }
        used[bi] = true;
        g_top[k] = bi;
    }
    for (int c = 0; c < 10; c++) {
        float a = 0.0f;
        for (int h = 0; h < 16; h++) a += W2[h] * W1[h * 10 + c];
        g_weff[c] = a;
    }
    float be = b2[0];
    for (int h = 0; h < 16; h++) be += W2[h] * b1[h];
    g_weff[10] = be;
}

// ---------------- Y combos -----------------------------------------------------
__global__ void ycombo_kernel(const float* __restrict__ x) {
    const float* X1 = x + (size_t)g_top[1] * NN;
    const float* X2 = x + (size_t)g_top[2] * NN;
    const float* X3 = x + (size_t)g_top[3] * NN;
    float w0 = g_weff[0], w1 = g_weff[1], w2 = g_weff[2];
    float w3 = g_weff[3], w4 = g_weff[4], w5 = g_weff[5];
    for (int e = blockIdx.x * blockDim.x + threadIdx.x; e < NN;
         e += gridDim.x * blockDim.x) {
        float a = X1[e], b = X2[e], c = X3[e];
        g_y[e]          = w0 * a + w1 * b + w2 * c;
        g_y[NN + e]     = w3 * b + w4 * c;
        g_y[2 * NN + e] = w5 * c;
    }
}

// ---------------- pair GEMM: X (1024x3072) @ Y (3072x1024), split-K=4 ----------
__global__ __launch_bounds__(256) void pair_gemm(const float* __restrict__ x) {
    __shared__ float As[16][132];
    __shared__ float Bs[16][128];
    int z = blockIdx.z;
    int row0 = blockIdx.y * 128, c0 = blockIdx.x * 128;
    const float* A0 = x + (size_t)g_top[0] * NN;
    const float* A1 = x + (size_t)g_top[1] * NN;
    const float* A2 = x + (size_t)g_top[2] * NN;
    int tid = threadIdx.x;
    float acc[8][8] = {};
    int k0 = z * 768;
    for (int kt = 0; kt < 48; kt++) {
        int kg = k0 + kt * 16;
        const float* Ap = (kg < 1024) ? A0 : ((kg < 2048) ? A1 : A2);
        int kl = kg & 1023;
        #pragma unroll
        for (int i = 0; i < 8; i++) {
            int l = tid + i * 256;
            int kk = l & 15, mm = l >> 4;
            As[kk][mm] = Ap[(size_t)(row0 + mm) * N + kl + kk];
        }
        #pragma unroll
        for (int i = 0; i < 8; i++) {
            int l = tid + i * 256;
            int nn = l & 127, kk = l >> 7;
            Bs[kk][nn] = g_y[(size_t)(kg + kk) * N + c0 + nn];
        }
        __syncthreads();
        int mm0 = (tid >> 4) * 8, nn0 = (tid & 15) * 8;
        #pragma unroll
        for (int kk = 0; kk < 16; kk++) {
            float a[8], b[8];
            *(float4*)&a[0] = *(const float4*)&As[kk][mm0];
            *(float4*)&a[4] = *(const float4*)&As[kk][mm0 + 4];
            *(float4*)&b[0] = *(const float4*)&Bs[kk][nn0];
            *(float4*)&b[4] = *(const float4*)&Bs[kk][nn0 + 4];
            #pragma unroll
            for (int i = 0; i < 8; i++)
                #pragma unroll
                for (int j = 0; j < 8; j++)
                    acc[i][j] = fmaf(a[i], b[j], acc[i][j]);
        }
        __syncthreads();
    }
    float* P = g_part + (size_t)z * NN;
    int mm0 = (tid >> 4) * 8, nn0 = (tid & 15) * 8;
    #pragma unroll
    for (int i = 0; i < 8; i++) {
        float4 v0 = {acc[i][0], acc[i][1], acc[i][2], acc[i][3]};
        float4 v1 = {acc[i][4], acc[i][5], acc[i][6], acc[i][7]};
        size_t off = (size_t)(row0 + mm0 + i) * N + c0 + nn0;
        *(float4*)&P[off] = v0;
        *(float4*)&P[off + 4] = v1;
    }
}

// ---------------- epilogue -----------------------------------------------------
__global__ void final_kernel(const float* __restrict__ x, float* __restrict__ out,
                             int out_size) {
    int gate = g_gate;
    const float* P4 = x + (size_t)g_top[4] * NN;
    const float* P5 = x + (size_t)g_top[5] * NN;
    const float* P6 = x + (size_t)g_top[6] * NN;
    const float* P7 = x + (size_t)g_top[7] * NN;
    float w6 = g_weff[6], w7 = g_weff[7], w8 = g_weff[8], w9 = g_weff[9];
    float be = g_weff[10];
    for (int i = blockIdx.x * blockDim.x + threadIdx.x; i < out_size;
         i += gridDim.x * blockDim.x) {
        if (i < NN) {
            float s = (g_part[i] + g_part[NN + i]) + (g_part[2 * NN + i] + g_part[3 * NN + i])
                    + w6 * P4[i] + w7 * P5[i] + w8 * P6[i] + w9 * P7[i] + be;
            out[i] = gate ? (s / (1.0f + expf(-s))) : 0.0f;
        } else {
            out[i] = gate ? 1.0f : 0.0f;
        }
    }
}

// ---------------- host driver --------------------------------------------------
extern "C" void kernel_launch(void* const* d_in, const int* in_sizes, int n_in,
                              void* d_out, int out_size) {
    const float* x = (const float*)d_in[0];
    const int* flags = (const int*)d_in[1];
    const float* W1 = (const float*)d_in[2];
    const float* b1 = (const float*)d_in[3];
    const float* W2 = (const float*)d_in[4];
    const float* b2 = (const float*)d_in[5];
    float* out = (float*)d_out;

    const size_t lu_smem = 128 * 132 * 4;   // 67,584 B (tail is the max phase)
    cudaFuncSetAttribute(lu_persistent, cudaFuncAttributeMaxDynamicSharedMemorySize,
                         lu_smem);

    reset_kernel<<<1, 32>>>();
    lu_persistent<<<NMAT * GPM, 256, lu_smem>>>((const float4*)x);
    topk_kernel<<<1, 32>>>(flags, W1, b1, W2, b2);
    ycombo_kernel<<<1024, 256>>>(x);
    pair_gemm<<<dim3(8, 8, 4), 256>>>(x);
    final_kernel<<<1024, 256>>>(x, out, out_size);
}

// round 14
// speedup vs baseline: 1.6342x; 1.0218x over previous
#include <cuda_runtime.h>
#include <math.h>

#define N 1024
#define NN (N*N)
#define NB 32
#define NPAN 28      // panels 0..27; last 128 cols by tail kernel
#define NGRP 4
#define GSZ  4       // matrices per group

// ---------------- scratch (device globals) -------------------------------------
__device__ float g_lu[16 * NN];          // LU workspace
__device__ float g_u12[16 * 32 * N];     // staged U12 per step
__device__ float g_l21[16 * N * 32];     // staged L21 (position-major)
__device__ float g_diag[16 * 32 * 33];   // factored 32x32 diag block (L\U)
__device__ float g_invd[16 * 32];        // 1/U11 diag
__device__ int   g_rowmap[16 * N];       // logical->physical row map
__device__ float g_y[3 * NN];
__device__ float g_part[4 * NN];
__device__ float g_scores[16];
__device__ int   g_top[8];
__device__ int   g_gate;
__device__ float g_weff[11];

// ---------------- init: copy x, identity map -----------------------------------
__global__ void init_kernel(const float4* __restrict__ x4) {
    size_t n4 = (size_t)16 * NN / 4;
    for (size_t i = (size_t)blockIdx.x * blockDim.x + threadIdx.x; i < n4;
         i += (size_t)gridDim.x * blockDim.x)
        ((float4*)g_lu)[i] = x4[i];
    for (int i = blockIdx.x * blockDim.x + threadIdx.x; i < 16 * N;
         i += gridDim.x * blockDim.x)
        g_rowmap[i] = i & (N - 1);
}

// ---------------- panel: window-pivoted 128x32 factor in smem ------------------
__global__ __launch_bounds__(256) void panel_kernel(int kb, int m0) {
    __shared__ float sp[128][33];
    int m = m0 + blockIdx.x, tid = threadIdx.x, lane = tid & 31;
    int col0 = kb * NB;
    int Ru = N - col0;
    int Wn = Ru < 128 ? Ru : 128;
    float* A = g_lu + (size_t)m * NN;
    int* map = g_rowmap + m * N;

    for (int l = tid; l < Wn * 32; l += 256) {
        int w = l >> 5, c = l & 31;
        sp[w][c] = A[(size_t)map[col0 + w] * N + col0 + c];
    }
    __syncthreads();

    float logsum = 0.0f;
    for (int j = 0; j < 32; j++) {
        float bv = -1.0f; int bp = 1 << 30;
        #pragma unroll
        for (int q = 0; q < 4; q++) {
            int w = lane + 32 * q;
            if (w >= j && w < Wn) {
                float v = fabsf(sp[w][j]);
                if (v > bv || (v == bv && w < bp)) { bv = v; bp = w; }
            }
        }
        #pragma unroll
        for (int off = 16; off; off >>= 1) {
            float ov = __shfl_xor_sync(0xffffffffu, bv, off);
            int   op = __shfl_xor_sync(0xffffffffu, bp, off);
            if (ov > bv || (ov == bv && op < bp)) { bv = ov; bp = op; }
        }
        int piv = bp;
        float pv = sp[piv][j];
        float inv = 1.0f / pv;
        if (tid == 0) logsum += logf(fabsf(pv));
        __syncthreads();
        if (piv != j) {
            if (tid < 32) {
                float t = sp[j][tid];
                sp[j][tid] = sp[piv][tid];
                sp[piv][tid] = t;
            }
            if (tid == 0) {
                int t = map[col0 + j];
                map[col0 + j] = map[col0 + piv];
                map[col0 + piv] = t;
            }
        }
        __syncthreads();
        int r = j + 1 + tid;
        if (r < Wn) {
            float lij = sp[r][j] * inv;
            sp[r][j] = lij;
            for (int c = j + 1; c < 32; c++)
                sp[r][c] -= lij * sp[j][c];
        }
        __syncthreads();
    }

    if (tid == 0) {
        if (kb == 0) g_scores[m] = logsum;
        else         g_scores[m] += logsum;
    }
    for (int l = tid; l < 32 * 32; l += 256)
        g_diag[m * 32 * 33 + (l >> 5) * 33 + (l & 31)] = sp[l >> 5][l & 31];
    if (tid < 32) g_invd[m * 32 + tid] = 1.0f / sp[tid][tid];
    for (int l = tid; l < (Wn - 32) * 32; l += 256) {
        int p = l >> 5, c = l & 31;
        g_l21[((size_t)m * N + p) * 32 + c] = sp[p + 32][c];
    }
}

// ---------------- lstage: U12 = L11^-1 A12 ; L21 = A21 U11^-1 ------------------
__global__ __launch_bounds__(128) void lstage_kernel(int kb, int ct, int m0) {
    __shared__ float d[32][33];
    __shared__ float dinv[32];
    int m = m0 + blockIdx.y, tid = threadIdx.x;
    int col0 = kb * NB, nb0 = col0 + NB;
    for (int l = tid; l < 32 * 33; l += 128)
        ((float*)d)[l] = g_diag[m * 32 * 33 + l];
    if (tid < 32) dinv[tid] = g_invd[m * 32 + tid];
    __syncthreads();
    const int* map = g_rowmap + m * N;
    const float* A = g_lu + (size_t)m * NN;

    if (blockIdx.x < ct) {
        int cc = nb0 + blockIdx.x * 128 + tid;
        if (cc < N) {
            float u[32];
            float* U = g_u12 + (size_t)m * 32 * N;
            #pragma unroll
            for (int j = 0; j < 32; j++) {
                float s = A[(size_t)map[col0 + j] * N + cc];
                #pragma unroll 31
                for (int i = 0; i < 31; i++)
                    if (i < j) s -= d[j][i] * u[i];
                u[j] = s;
                U[j * N + cc] = s;
            }
        }
    } else {
        int lr = col0 + 128 + (blockIdx.x - ct) * 128 + tid;
        if (lr < N) {
            const float* ar = A + (size_t)map[lr] * N + col0;
            float* lrow = g_l21 + ((size_t)m * N + (lr - nb0)) * 32;
            float xv[32];
            #pragma unroll
            for (int j = 0; j < 32; j++) {
                float s = ar[j];
                #pragma unroll 31
                for (int i = 0; i < 31; i++)
                    if (i < j) s -= xv[i] * d[i][j];
                xv[j] = s * dinv[j];
                lrow[j] = xv[j];
            }
        }
    }
}

// ---------------- update: A22 -= L21 @ U12 (128x128 tiles, 2 CTA/SM) -----------
__global__ __launch_bounds__(256, 2) void update_kernel(int kb, int m0) {
    __shared__ float Bs[32][128];
    __shared__ float LsT[32][132];
    int m = m0 + blockIdx.z, tid = threadIdx.x;
    int col0 = kb * NB, nb0 = col0 + NB;
    int RC = N - nb0;
    const int* map = g_rowmap + m * N;
    float* A = g_lu + (size_t)m * NN;
    const float* U = g_u12 + (size_t)m * 32 * N;
    const float* L = g_l21 + (size_t)m * N * 32;
    int c0 = nb0 + blockIdx.x * 128;
    int r0p = blockIdx.y * 128;

    #pragma unroll
    for (int i = 0; i < 16; i++) {
        int l = tid + i * 256;
        int c = l & 127, kk = l >> 7;
        int cc = c0 + c;
        Bs[kk][c] = (cc < N) ? U[kk * N + cc] : 0.0f;
    }
    #pragma unroll
    for (int i = 0; i < 16; i++) {
        int l = tid + i * 256;
        int r = l >> 5, kk = l & 31;
        int p = r0p + r;
        LsT[kk][r] = (p < RC) ? L[(size_t)p * 32 + kk] : 0.0f;
    }
    __syncthreads();

    int tx = tid & 15, ty = tid >> 4;
    float acc[8][8] = {};
    #pragma unroll
    for (int kk = 0; kk < 32; kk++) {
        float a[8], b[8];
        *(float4*)&a[0] = *(const float4*)&LsT[kk][ty * 8];
        *(float4*)&a[4] = *(const float4*)&LsT[kk][ty * 8 + 4];
        *(float4*)&b[0] = *(const float4*)&Bs[kk][tx * 8];
        *(float4*)&b[4] = *(const float4*)&Bs[kk][tx * 8 + 4];
        #pragma unroll
        for (int i = 0; i < 8; i++)
            #pragma unroll
            for (int j = 0; j < 8; j++)
                acc[i][j] = fmaf(a[i], b[j], acc[i][j]);
    }
    int gc0 = c0 + tx * 8;
    if (gc0 < N) {
        #pragma unroll
        for (int i = 0; i < 8; i++) {
            int p = r0p + ty * 8 + i;
            if (p < RC) {
                float4* pp = (float4*)&A[(size_t)map[nb0 + p] * N + gc0];
                float4 v0 = pp[0], v1 = pp[1];
                v0.x -= acc[i][0]; v0.y -= acc[i][1]; v0.z -= acc[i][2]; v0.w -= acc[i][3];
                v1.x -= acc[i][4]; v1.y -= acc[i][5]; v1.z -= acc[i][6]; v1.w -= acc[i][7];
                pp[0] = v0; pp[1] = v1;
            }
        }
    }
}

// ---------------- tail: full pivoted factor of trailing 128x128 (logdet) -------
__global__ __launch_bounds__(256) void tail_kernel(int m0) {
    extern __shared__ float st[];         // 128 x 132
    __shared__ float rv[8];
    __shared__ int   rr[8];
    __shared__ float s_u;
    __shared__ int   s_p;
    int m = m0 + blockIdx.x, tid = threadIdx.x;
    const float* A = g_lu + (size_t)m * NN;
    const int* map = g_rowmap + m * N;
    const int nb0 = N - 128;

    for (int l = tid; l < 128 * 128; l += 256) {
        int r = l >> 7, c = l & 127;
        st[r * 132 + c] = A[(size_t)map[nb0 + r] * N + nb0 + c];
    }
    __syncthreads();

    float logsum = 0.0f;
    for (int j = 0; j < 128; j++) {
        float bv = -1.0f; int br = j;
        if (tid < 128 && tid >= j) {
            bv = fabsf(st[tid * 132 + j]);
            br = tid;
        }
        #pragma unroll
        for (int off = 16; off; off >>= 1) {
            float ov = __shfl_down_sync(0xffffffffu, bv, off);
            int   orr = __shfl_down_sync(0xffffffffu, br, off);
            if (ov > bv || (ov == bv && orr < br)) { bv = ov; br = orr; }
        }
        if ((tid & 31) == 0) { rv[tid >> 5] = bv; rr[tid >> 5] = br; }
        __syncthreads();
        if (tid == 0) {
            float b0 = rv[0]; int r0 = rr[0];
            for (int w = 1; w < 8; w++)
                if (rv[w] > b0 || (rv[w] == b0 && rr[w] < r0)) { b0 = rv[w]; r0 = rr[w]; }
            s_p = r0;
            s_u = st[r0 * 132 + j];
            logsum += logf(fabsf(s_u));
        }
        __syncthreads();
        int p = s_p;
        float u = s_u;
        if (tid < 128 && p != j) {
            float t = st[j * 132 + tid];
            st[j * 132 + tid] = st[p * 132 + tid];
            st[p * 132 + tid] = t;
        }
        __syncthreads();
        if (tid < 128 && tid > j) {
            float lij = st[tid * 132 + j] / u;
            for (int c = j + 1; c < 128; c++)
                st[tid * 132 + c] -= lij * st[j * 132 + c];
        }
        __syncthreads();
    }
    if (tid == 0) g_scores[m] += logsum;
}

// ---------------- top-8 + effective-weight collapse ----------------------------
__global__ void topk_kernel(const int* __restrict__ flags_i32,
                            const float* __restrict__ W1, const float* __restrict__ b1,
                            const float* __restrict__ W2, const float* __restrict__ b2) {
    if (threadIdx.x != 0) return;
    const unsigned char* flags_u8 = (const unsigned char*)flags_i32;
    int w0 = flags_i32[0];
    bool as_bytes = (w0 > 1) || (w0 < 0);
    int f[16];
    for (int i = 0; i < 16; i++)
        f[i] = as_bytes ? (flags_u8[i] != 0) : (flags_i32[i] != 0);
    int s = 0;
    for (int i = 0; i < 16; i++) s += f[i];
    g_gate = (s >= 4) ? 1 : 0;
    const float NEG_INF = -__int_as_float(0x7f800000);
    float sc[16];
    for (int i = 0; i < 16; i++) sc[i] = f[i] ? g_scores[i] : NEG_INF;
    bool used[16] = {};
    for (int k = 0; k < 8; k++) {
        float best = NEG_INF;
        int bi = -1;
        for (int i = 0; i < 16; i++)
            if (!used[i] && (bi < 0 || sc[i] > best)) { best = sc[i]; bi = i; }
        used[bi] = true;
        g_top[k] = bi;
    }
    for (int c = 0; c < 10; c++) {
        float a = 0.0f;
        for (int h = 0; h < 16; h++) a += W2[h] * W1[h * 10 + c];
        g_weff[c] = a;
    }
    float be = b2[0];
    for (int h = 0; h < 16; h++) be += W2[h] * b1[h];
    g_weff[10] = be;
}

// ---------------- Y combos -----------------------------------------------------
__global__ void ycombo_kernel(const float* __restrict__ x) {
    const float* X1 = x + (size_t)g_top[1] * NN;
    const float* X2 = x + (size_t)g_top[2] * NN;
    const float* X3 = x + (size_t)g_top[3] * NN;
    float w0 = g_weff[0], w1 = g_weff[1], w2 = g_weff[2];
    float w3 = g_weff[3], w4 = g_weff[4], w5 = g_weff[5];
    for (int e = blockIdx.x * blockDim.x + threadIdx.x; e < NN;
         e += gridDim.x * blockDim.x) {
        float a = X1[e], b = X2[e], c = X3[e];
        g_y[e]          = w0 * a + w1 * b + w2 * c;
        g_y[NN + e]     = w3 * b + w4 * c;
        g_y[2 * NN + e] = w5 * c;
    }
}

// ---------------- pair GEMM: X (1024x3072) @ Y (3072x1024), split-K=4 ----------
__global__ __launch_bounds__(256) void pair_gemm(const float* __restrict__ x) {
    __shared__ float As[16][132];
    __shared__ float Bs[16][128];
    int z = blockIdx.z;
    int row0 = blockIdx.y * 128, c0 = blockIdx.x * 128;
    const float* A0 = x + (size_t)g_top[0] * NN;
    const float* A1 = x + (size_t)g_top[1] * NN;
    const float* A2 = x + (size_t)g_top[2] * NN;
    int tid = threadIdx.x;
    float acc[8][8] = {};
    int k0 = z * 768;
    for (int kt = 0; kt < 48; kt++) {
        int kg = k0 + kt * 16;
        const float* Ap = (kg < 1024) ? A0 : ((kg < 2048) ? A1 : A2);
        int kl = kg & 1023;
        #pragma unroll
        for (int i = 0; i < 8; i++) {
            int l = tid + i * 256;
            int kk = l & 15, mm = l >> 4;
            As[kk][mm] = Ap[(size_t)(row0 + mm) * N + kl + kk];
        }
        #pragma unroll
        for (int i = 0; i < 8; i++) {
            int l = tid + i * 256;
            int nn = l & 127, kk = l >> 7;
            Bs[kk][nn] = g_y[(size_t)(kg + kk) * N + c0 + nn];
        }
        __syncthreads();
        int mm0 = (tid >> 4) * 8, nn0 = (tid & 15) * 8;
        #pragma unroll
        for (int kk = 0; kk < 16; kk++) {
            float a[8], b[8];
            *(float4*)&a[0] = *(const float4*)&As[kk][mm0];
            *(float4*)&a[4] = *(const float4*)&As[kk][mm0 + 4];
            *(float4*)&b[0] = *(const float4*)&Bs[kk][nn0];
            *(float4*)&b[4] = *(const float4*)&Bs[kk][nn0 + 4];
            #pragma unroll
            for (int i = 0; i < 8; i++)
                #pragma unroll
                for (int j = 0; j < 8; j++)
                    acc[i][j] = fmaf(a[i], b[j], acc[i][j]);
        }
        __syncthreads();
    }
    float* P = g_part + (size_t)z * NN;
    int mm0 = (tid >> 4) * 8, nn0 = (tid & 15) * 8;
    #pragma unroll
    for (int i = 0; i < 8; i++) {
        float4 v0 = {acc[i][0], acc[i][1], acc[i][2], acc[i][3]};
        float4 v1 = {acc[i][4], acc[i][5], acc[i][6], acc[i][7]};
        size_t off = (size_t)(row0 + mm0 + i) * N + c0 + nn0;
        *(float4*)&P[off] = v0;
        *(float4*)&P[off + 4] = v1;
    }
}

// ---------------- epilogue -----------------------------------------------------
__global__ void final_kernel(const float* __restrict__ x, float* __restrict__ out,
                             int out_size) {
    int gate = g_gate;
    const float* P4 = x + (size_t)g_top[4] * NN;
    const float* P5 = x + (size_t)g_top[5] * NN;
    const float* P6 = x + (size_t)g_top[6] * NN;
    const float* P7 = x + (size_t)g_top[7] * NN;
    float w6 = g_weff[6], w7 = g_weff[7], w8 = g_weff[8], w9 = g_weff[9];
    float be = g_weff[10];
    for (int i = blockIdx.x * blockDim.x + threadIdx.x; i < out_size;
         i += gridDim.x * blockDim.x) {
        if (i < NN) {
            float s = (g_part[i] + g_part[NN + i]) + (g_part[2 * NN + i] + g_part[3 * NN + i])
                    + w6 * P4[i] + w7 * P5[i] + w8 * P6[i] + w9 * P7[i] + be;
            out[i] = gate ? (s / (1.0f + expf(-s))) : 0.0f;
        } else {
            out[i] = gate ? 1.0f : 0.0f;
        }
    }
}

// ---------------- host driver: fork-join multi-stream DAG ----------------------
extern "C" void kernel_launch(void* const* d_in, const int* in_sizes, int n_in,
                              void* d_out, int out_size) {
    const float* x = (const float*)d_in[0];
    const int* flags = (const int*)d_in[1];
    const float* W1 = (const float*)d_in[2];
    const float* b1 = (const float*)d_in[3];
    const float* W2 = (const float*)d_in[4];
    const float* b2 = (const float*)d_in[5];
    float* out = (float*)d_out;

    const size_t tail_smem = 128 * 132 * 4;   // 67.6 KB
    cudaFuncSetAttribute(tail_kernel, cudaFuncAttributeMaxDynamicSharedMemorySize,
                         tail_smem);

    cudaStream_t st[NGRP];
    cudaEvent_t evRoot, evG[NGRP];
    for (int g = 0; g < NGRP; g++)
        cudaStreamCreateWithFlags(&st[g], cudaStreamNonBlocking);
    cudaEventCreateWithFlags(&evRoot, cudaEventDisableTiming);
    for (int g = 0; g < NGRP; g++)
        cudaEventCreateWithFlags(&evG[g], cudaEventDisableTiming);

    // fork after init
    init_kernel<<<2048, 256>>>((const float4*)x);
    cudaEventRecord(evRoot, 0);

    for (int g = 0; g < NGRP; g++) {
        cudaStreamWaitEvent(st[g], evRoot, 0);
        int m0 = g * GSZ;
        for (int kb = 0; kb < NPAN; kb++) {
            panel_kernel<<<GSZ, 256, 0, st[g]>>>(kb, m0);
            int CC = N - NB * (kb + 1);        // >= 128 for kb <= 27
            int Ru = N - NB * kb;
            int ct = (CC + 127) / 128;
            int rtB = (Ru > 128) ? (Ru - 128 + 127) / 128 : 0;
            lstage_kernel<<<dim3(ct + rtB, GSZ), 128, 0, st[g]>>>(kb, ct, m0);
            update_kernel<<<dim3(ct, ct, GSZ), 256, 0, st[g]>>>(kb, m0);
        }
        tail_kernel<<<GSZ, 256, tail_smem, st[g]>>>(m0);
        cudaEventRecord(evG[g], st[g]);
    }

    // join back into capture-origin stream
    for (int g = 0; g < NGRP; g++)
        cudaStreamWaitEvent((cudaStream_t)0, evG[g], 0);

    topk_kernel<<<1, 32>>>(flags, W1, b1, W2, b2);
    ycombo_kernel<<<1024, 256>>>(x);
    pair_gemm<<<dim3(8, 8, 4), 256>>>(x);
    final_kernel<<<1024, 256>>>(x, out, out_size);

    for (int g = 0; g < NGRP; g++) {
        cudaStreamDestroy(st[g]);
        cudaEventDestroy(evG[g]);
    }
    cudaEventDestroy(evRoot);
}